// round 17
// baseline (speedup 1.0000x reference)
#include <cuda_runtime.h>
#include <cuda_fp16.h>
#include <math.h>
#include <stdint.h>

#define B_  128
#define T_  64
#define F_  2048
#define H_  1024
#define M_  512
#define G4  4096   // 4*H
#define NA  4608   // 4H + M
#define K2  2048   // 2H

// ---------------- device scratch (no allocations allowed) -------------------
__device__ __align__(128) __half d_VidH[(size_t)B_*T_*F_];
__device__ __align__(128) __half d_VidL[(size_t)B_*T_*F_];
__device__ __align__(128) __half d_WembH[(size_t)H_*F_];
__device__ __align__(128) __half d_WembL[(size_t)H_*F_];
__device__ __align__(128) __half d_VH[(size_t)B_*T_*H_];
__device__ __align__(128) __half d_VL[(size_t)B_*T_*H_];
__device__ __align__(128) __half d_WxH[(size_t)NA*H_];
__device__ __align__(128) __half d_WxL[(size_t)NA*H_];
__device__ __align__(128) __half d_WhH[(size_t)NA*H_];
__device__ __align__(128) __half d_WhL[(size_t)NA*H_];
__device__ __align__(128) __half d_WbH[(size_t)G4*K2];
__device__ __align__(128) __half d_WbL[(size_t)G4*K2];
__device__ __align__(128) __half d_AhH[B_*H_];
__device__ __align__(128) __half d_AhL[B_*H_];
__device__ __align__(128) __half d_STH[B_*K2];

__device__ float d_bx [NA];
__device__ float d_GXZ[(size_t)B_*T_*NA];    // rows t*B+b
__device__ float d_Y1 [B_*NA];
__device__ float d_Y2 [B_*G4];
__device__ float d_c1 [B_*H_];
__device__ float d_c2 [B_*H_];
__device__ float d_s  [B_];
__device__ unsigned int d_bars[260];

// ---------------- asm helpers ------------------------------------------------
__device__ __forceinline__ uint32_t s2u_(const void* p) {
    uint32_t a;
    asm("{ .reg .u64 t; cvta.to.shared.u64 t, %1; cvt.u32.u64 %0, t; }" : "=r"(a) : "l"(p));
    return a;
}
__device__ __forceinline__ void cp16_(uint32_t d, const void* s) {
    asm volatile("cp.async.cg.shared.global [%0], [%1], 16;" :: "r"(d), "l"(s));
}
__device__ __forceinline__ void ldsm4_(uint32_t a, uint32_t& r0, uint32_t& r1, uint32_t& r2, uint32_t& r3) {
    asm volatile("ldmatrix.sync.aligned.m8n8.x4.shared.b16 {%0,%1,%2,%3}, [%4];"
                 : "=r"(r0), "=r"(r1), "=r"(r2), "=r"(r3) : "r"(a));
}
__device__ __forceinline__ void hmma_(float* c, const uint32_t* a, const uint32_t* b) {
    asm volatile("mma.sync.aligned.m16n8k16.row.col.f32.f16.f16.f32 "
                 "{%0,%1,%2,%3}, {%4,%5,%6,%7}, {%8,%9}, {%0,%1,%2,%3};"
                 : "+f"(c[0]), "+f"(c[1]), "+f"(c[2]), "+f"(c[3])
                 : "r"(a[0]), "r"(a[1]), "r"(a[2]), "r"(a[3]), "r"(b[0]), "r"(b[1]));
}
__device__ __forceinline__ float sigm(float x) { return 1.f / (1.f + expf(-x)); }

// ---------------- precompute HMMA GEMM: 128x128 tiles, BK=32 -----------------
// 8 warps = 4M x 2N (warp 32 x 64). PASSES=3: 2-stage; PASSES=2: 3-stage.
// stage: A (128 hi [+128 lo]) x 80B, then B 256 rows x 80B.

template<int HAS_BIAS, int RELU, int SPLIT_OUT, int PASSES>
__global__ __launch_bounds__(256)
void gemm_h(const __half* __restrict__ AH, const __half* __restrict__ AL,
            size_t tileStride, int lda,
            const __half* __restrict__ BH, const __half* __restrict__ BL,
            float* __restrict__ C,
            const float* __restrict__ bias,
            __half* __restrict__ OH, __half* __restrict__ OL,
            int K, int N, int bxOff)
{
    constexpr int ASZ  = (PASSES == 3) ? 20480 : 10240;
    constexpr int STG  = ASZ + 20480;
    constexpr int NSTG = (PASSES == 3) ? 2 : 3;

    extern __shared__ __align__(128) char sm[];
    const uint32_t sb = s2u_(sm);
    const int tid  = threadIdx.x;
    const int lane = tid & 31;
    const int wid  = tid >> 5;
    const int wm   = wid & 3;
    const int wn   = wid >> 2;
    const int bx   = blockIdx.x + bxOff, by = blockIdx.y;

    const __half* gAH = AH + (size_t)by * tileStride;
    const __half* gAL = AL + (size_t)by * tileStride;
    const __half* gBH = BH + (size_t)bx * 128 * K;
    const __half* gBL = BL + (size_t)bx * 128 * K;

    float acc[2][8][4];
#pragma unroll
    for (int i = 0; i < 2; i++)
#pragma unroll
        for (int j = 0; j < 8; j++)
#pragma unroll
            for (int q = 0; q < 4; q++) acc[i][j][q] = 0.f;

    auto load_stage = [&](int p, int kt) {
        const uint32_t dst = sb + p * STG;
        const int k0 = kt * 32;
        if (PASSES == 3 || tid < 128) {
            const __half* src = (tid < 128) ? (gAH + (size_t)tid * lda)
                                            : (gAL + (size_t)(tid - 128) * lda);
#pragma unroll
            for (int col = 0; col < 4; col++)
                cp16_(dst + tid * 80 + col * 16, src + k0 + col * 8);
        }
        {
            const __half* src = (tid < 128) ? (gBH + (size_t)tid * K)
                                            : (gBL + (size_t)(tid - 128) * K);
#pragma unroll
            for (int col = 0; col < 4; col++)
                cp16_(dst + ASZ + tid * 80 + col * 16, src + k0 + col * 8);
        }
        asm volatile("cp.async.commit_group;" ::: "memory");
    };

    const int KT = K / 32;
    load_stage(0, 0);
    if (NSTG == 3 && KT > 1) load_stage(1, 1);
    const int rsel = lane & 15, csel = lane >> 4;

    for (int kt = 0; kt < KT; kt++) {
        if (NSTG == 2) {
            if (kt + 1 < KT) {
                load_stage((kt + 1) & 1, kt + 1);
                asm volatile("cp.async.wait_group 1;" ::: "memory");
            } else {
                asm volatile("cp.async.wait_group 0;" ::: "memory");
            }
        } else {
            if (kt + 2 < KT) {
                load_stage((kt + 2) % 3, kt + 2);
                asm volatile("cp.async.wait_group 2;" ::: "memory");
            } else if (kt + 1 < KT) {
                asm volatile("cp.async.wait_group 1;" ::: "memory");
            } else {
                asm volatile("cp.async.wait_group 0;" ::: "memory");
            }
        }
        __syncthreads();
        const uint32_t stg = sb + (kt % NSTG) * STG;
#pragma unroll
        for (int h = 0; h < 2; h++) {
            uint32_t aH[2][4], aL[2][4];
#pragma unroll
            for (int mi = 0; mi < 2; mi++) {
                uint32_t ad = stg + (wm * 32 + mi * 16 + rsel) * 80 + h * 32 + csel * 16;
                ldsm4_(ad, aH[mi][0], aH[mi][1], aH[mi][2], aH[mi][3]);
                if (PASSES == 3)
                    ldsm4_(ad + 10240, aL[mi][0], aL[mi][1], aL[mi][2], aL[mi][3]);
            }
#pragma unroll
            for (int g = 0; g < 4; g++) {
                uint32_t bd = stg + ASZ + (wn * 64 + g * 16 + rsel) * 80 + h * 32 + csel * 16;
                uint32_t t0, t1, t2, t3;
                uint32_t bH[2][2], bL[2][2];
                ldsm4_(bd, t0, t1, t2, t3);
                bH[0][0] = t0; bH[0][1] = t2; bH[1][0] = t1; bH[1][1] = t3;
                ldsm4_(bd + 10240, t0, t1, t2, t3);
                bL[0][0] = t0; bL[0][1] = t2; bL[1][0] = t1; bL[1][1] = t3;
#pragma unroll
                for (int mi = 0; mi < 2; mi++)
#pragma unroll
                    for (int nj = 0; nj < 2; nj++) {
                        float* a = acc[mi][g * 2 + nj];
                        hmma_(a, aH[mi], bH[nj]);
                        hmma_(a, aH[mi], bL[nj]);
                        if (PASSES == 3)
                            hmma_(a, aL[mi], bH[nj]);
                    }
            }
        }
        __syncthreads();
    }

#pragma unroll
    for (int mi = 0; mi < 2; mi++)
#pragma unroll
        for (int ni = 0; ni < 8; ni++) {
            const int row0 = by * 128 + wm * 32 + mi * 16 + (lane >> 2);
            const int col  = bx * 128 + wn * 64 + ni * 8 + (lane & 3) * 2;
            float v[4];
#pragma unroll
            for (int q = 0; q < 4; q++) v[q] = acc[mi][ni][q];
            if (HAS_BIAS) {
                float b0 = bias[col], b1 = bias[col + 1];
                v[0] += b0; v[1] += b1; v[2] += b0; v[3] += b1;
            }
            if (RELU) {
#pragma unroll
                for (int q = 0; q < 4; q++) v[q] = fmaxf(v[q], 0.f);
            }
            if (SPLIT_OUT) {
#pragma unroll
                for (int q = 0; q < 4; q++) {
                    int r = row0 + (q >> 1) * 8, c = col + (q & 1);
                    __half hi = __float2half(v[q]);
                    __half lo = __float2half(v[q] - __half2float(hi));
                    OH[(size_t)r * N + c] = hi;
                    OL[(size_t)r * N + c] = lo;
                }
            } else {
                *reinterpret_cast<float2*>(&C[(size_t)row0 * N + col])       = make_float2(v[0], v[1]);
                *reinterpret_cast<float2*>(&C[(size_t)(row0 + 8) * N + col]) = make_float2(v[2], v[3]);
            }
        }
}

// ---------------- persistent scan: 128x32 tiles, 8 warps (8M x 1N), 3-stage --
// stage (uniform 25600B): A hi 128x80 [0,10240), A lo [10240,20480), B 64x80 [20480,25600)
constexpr int SSTG = 25600;
constexpr int SCAN_SMEM = 3 * SSTG + 1024;   // + reduction buffer

template<int PASSES>
__device__ __forceinline__ void tile_mm128(
    const __half* __restrict__ AH, const __half* __restrict__ AL, int lda,
    const __half* __restrict__ BH, const __half* __restrict__ BL, int ldb,
    int KT, uint32_t sbase, float acc[4][4],
    int tid, int wid, int rsel, int csel)
{
    auto load_stage = [&](int p, int kt) {
        const uint32_t dst = sbase + p * SSTG;
        const int k0 = kt * 32;
#pragma unroll
        for (int i = 0; i < 2; i++) {      // A: 512 chunks (hi), +512 (lo, 3-pass)
            int c = tid * 2 + i;
            int row = c >> 2, col = c & 3;
            cp16_(dst + row * 80 + col * 16, AH + (size_t)row * lda + k0 + col * 8);
            if (PASSES == 3)
                cp16_(dst + 10240 + row * 80 + col * 16, AL + (size_t)row * lda + k0 + col * 8);
        }
        {   // B: 64 rows (32 hi + 32 lo), 256 chunks, 1/thread
            int row = tid >> 2, col = tid & 3;
            const __half* src = (row < 32) ? BH + (size_t)row * ldb
                                           : BL + (size_t)(row - 32) * ldb;
            cp16_(dst + 20480 + row * 80 + col * 16, src + k0 + col * 8);
        }
        asm volatile("cp.async.commit_group;" ::: "memory");
    };

    load_stage(0, 0);
    if (KT > 1) load_stage(1, 1);

    for (int kt = 0; kt < KT; kt++) {
        if (kt + 2 < KT) {
            load_stage((kt + 2) % 3, kt + 2);
            asm volatile("cp.async.wait_group 2;" ::: "memory");
        } else if (kt + 1 < KT) {
            asm volatile("cp.async.wait_group 1;" ::: "memory");
        } else {
            asm volatile("cp.async.wait_group 0;" ::: "memory");
        }
        __syncthreads();

        const uint32_t stg = sbase + (kt % 3) * SSTG;
#pragma unroll
        for (int h = 0; h < 2; h++) {
            uint32_t aH[4], aL[4], bH[4][2], bL[4][2];
            {
                uint32_t ad = stg + (wid * 16 + rsel) * 80 + h * 32 + csel * 16;
                ldsm4_(ad, aH[0], aH[1], aH[2], aH[3]);
                if (PASSES == 3)
                    ldsm4_(ad + 10240, aL[0], aL[1], aL[2], aL[3]);
            }
#pragma unroll
            for (int g = 0; g < 2; g++) {
                uint32_t bd = stg + 20480 + (g * 16 + rsel) * 80 + h * 32 + csel * 16;
                uint32_t t0, t1, t2, t3;
                ldsm4_(bd, t0, t1, t2, t3);
                bH[g*2][0] = t0; bH[g*2][1] = t2; bH[g*2+1][0] = t1; bH[g*2+1][1] = t3;
                ldsm4_(bd + 2560, t0, t1, t2, t3);
                bL[g*2][0] = t0; bL[g*2][1] = t2; bL[g*2+1][0] = t1; bL[g*2+1][1] = t3;
            }
#pragma unroll
            for (int nf = 0; nf < 4; nf++) {
                hmma_(acc[nf], aH, bH[nf]);
                hmma_(acc[nf], aH, bL[nf]);
                if (PASSES == 3)
                    hmma_(acc[nf], aL, bH[nf]);
            }
        }
        __syncthreads();
    }
}

__global__ __launch_bounds__(256)
void scan_persist(const float* __restrict__ vs, float* __restrict__ out)
{
    extern __shared__ __align__(128) char smem[];
    const uint32_t sbase = s2u_(smem);
    float* red = reinterpret_cast<float*>(smem + 3 * SSTG);
    const int tid  = threadIdx.x;
    const int lane = tid & 31;
    const int wid  = tid >> 5;
    const int rsel = lane & 15, csel = lane >> 4;
    const int cta  = blockIdx.x;
    const int G    = gridDim.x;
    int bar = 0;

    auto gbar = [&]() {
        __threadfence();
        __syncthreads();
        if (tid == 0) {
            atomicAdd(&d_bars[bar], 1u);
            while (*((volatile unsigned int*)&d_bars[bar]) < (unsigned)G) { }
        }
        bar++;
        __syncthreads();
        __threadfence();
    };

    // LSTM2 + c2/h2 commit (runs inside the NEXT step's P1 phase)
    auto do_p4 = [&](bool last) {
        const int b = cta - (G - B_);
        if (b >= 0 && b < B_) {
            const float* Yb = d_Y2 + (size_t)b * G4;
            for (int j = tid; j < H_; j += 256) {
                const int idx = b * H_ + j;
                float gi = Yb[j], gf = Yb[H_ + j], gg = Yb[2 * H_ + j], go = Yb[3 * H_ + j];
                float c = sigm(gf) * d_c2[idx] + sigm(gi) * tanhf(gg);
                float h = sigm(go) * tanhf(c);
                d_c2[idx] = c;
                d_STH[b * K2 + H_ + j] = __float2half(h);
                if (last) out[idx] = h;
            }
        }
    };

    for (int t = 0; t < T_; t++) {
        // ---- phase A: P4(t-1) + P1: Y1 = h1 @ [Whh1;Wsh]^T + GXZ[t] (144 tiles 128x32)
        if (t > 0) do_p4(false);
        for (int n = cta; n < 144; n += G) {
            float acc[4][4];
#pragma unroll
            for (int j = 0; j < 4; j++)
#pragma unroll
                for (int q = 0; q < 4; q++) acc[j][q] = 0.f;
            if (n >= 128)
                tile_mm128<3>(d_AhH, d_AhL, H_,
                              d_WhH + (size_t)(n * 32) * H_, d_WhL + (size_t)(n * 32) * H_, H_,
                              H_ / 32, sbase, acc, tid, wid, rsel, csel);
            else
                tile_mm128<2>(d_AhH, d_AhL, H_,
                              d_WhH + (size_t)(n * 32) * H_, d_WhL + (size_t)(n * 32) * H_, H_,
                              H_ / 32, sbase, acc, tid, wid, rsel, csel);
            const float* gx = d_GXZ + (size_t)t * B_ * NA;
#pragma unroll
            for (int nf = 0; nf < 4; nf++) {
                const int r0 = wid * 16 + (lane >> 2);
                const int c0 = n * 32 + nf * 8 + (lane & 3) * 2;
                float2 g0 = *reinterpret_cast<const float2*>(&gx[(size_t)r0 * NA + c0]);
                float2 g1 = *reinterpret_cast<const float2*>(&gx[(size_t)(r0 + 8) * NA + c0]);
                *reinterpret_cast<float2*>(&d_Y1[(size_t)r0 * NA + c0]) =
                    make_float2(acc[nf][0] + g0.x, acc[nf][1] + g0.y);
                *reinterpret_cast<float2*>(&d_Y1[(size_t)(r0 + 8) * NA + c0]) =
                    make_float2(acc[nf][2] + g1.x, acc[nf][3] + g1.y);
            }
        }
        gbar();

        // ---- P2: boundary gate + LSTM1 + state commit
        for (int b = cta; b < B_; b += G) {
            const float* Yb = d_Y1 + (size_t)b * NA;
            float p = Yb[G4 + tid] * vs[tid] + Yb[G4 + 256 + tid] * vs[256 + tid];
            red[tid] = p;
            __syncthreads();
            for (int off = 128; off > 0; off >>= 1) {
                if (tid < off) red[tid] += red[tid + off];
                __syncthreads();
            }
            float s = rintf(1.f / (1.f + expf(-red[0])));
            if (tid == 0) d_s[b] = s;
            __syncthreads();
            for (int j = tid; j < H_; j += 256) {
                const int idx = b * H_ + j;
                float gi = Yb[j], gf = Yb[H_ + j], gg = Yb[2 * H_ + j], go = Yb[3 * H_ + j];
                float c = sigm(gf) * d_c1[idx] + sigm(gi) * tanhf(gg);
                float h = sigm(go) * tanhf(c);
                d_STH[b * K2 + j] = __float2half(h * s);
                float h1n = h * (1.f - s);
                d_c1[idx] = c * (1.f - s);
                __half hi = __float2half(h1n);
                __half lo = __float2half(h1n - __half2float(hi));
                d_AhH[idx] = hi;
                d_AhL[idx] = lo;
            }
        }
        gbar();

        // ---- P3: Y2 = [h1r*s | h2] @ [Wih2|Whh2]^T  (128 tiles of 128x32), 2-pass
        for (int n = cta; n < 128; n += G) {
            float acc[4][4];
#pragma unroll
            for (int j = 0; j < 4; j++)
#pragma unroll
                for (int q = 0; q < 4; q++) acc[j][q] = 0.f;
            tile_mm128<2>(d_STH, nullptr, K2,
                          d_WbH + (size_t)(n * 32) * K2, d_WbL + (size_t)(n * 32) * K2, K2,
                          K2 / 32, sbase, acc, tid, wid, rsel, csel);
#pragma unroll
            for (int nf = 0; nf < 4; nf++) {
                const int r0 = wid * 16 + (lane >> 2);
                const int c0 = n * 32 + nf * 8 + (lane & 3) * 2;
                *reinterpret_cast<float2*>(&d_Y2[(size_t)r0 * G4 + c0]) =
                    make_float2(acc[nf][0], acc[nf][1]);
                *reinterpret_cast<float2*>(&d_Y2[(size_t)(r0 + 8) * G4 + c0]) =
                    make_float2(acc[nf][2], acc[nf][3]);
            }
        }
        gbar();
    }

    // trailing LSTM2 for t = T-1 (writes final output)
    do_p4(true);
}

// ---------------- fused prep kernels -----------------------------------------
__global__ void prep_state(const float* __restrict__ b1, const float* __restrict__ bbd)
{
    int i = blockIdx.x * blockDim.x + threadIdx.x;
    __half z = __float2half(0.f);
    if (i < B_ * H_) { d_c1[i] = 0.f; d_c2[i] = 0.f; d_AhH[i] = z; d_AhL[i] = z; }
    if (i < B_ * K2) d_STH[i] = z;
    if (i < 260) d_bars[i] = 0u;
    if (i < NA) d_bx[i] = (i < G4) ? b1[i] : bbd[i - G4];
}

__global__ void split_all(const float* __restrict__ Wemb,
                          const float* __restrict__ Wih1, const float* __restrict__ Wsi,
                          const float* __restrict__ Whh1, const float* __restrict__ Wsh,
                          const float* __restrict__ Wih2, const float* __restrict__ Whh2,
                          const float* __restrict__ video)
{
    const size_t SZ_WEMB = (size_t)H_ * F_;
    const size_t SZ_WX   = (size_t)NA * H_;
    const size_t SZ_WB   = (size_t)G4 * K2;
    const size_t SZ_VID  = (size_t)B_ * T_ * F_;
    size_t idx = (size_t)blockIdx.x * blockDim.x + threadIdx.x;
    float v; __half *Hh, *Ll; size_t o;
    if (idx < SZ_WEMB) {
        o = idx; v = Wemb[o]; Hh = d_WembH; Ll = d_WembL;
    } else if ((idx -= SZ_WEMB) < SZ_WX) {
        o = idx;
        v = (o < (size_t)G4 * H_) ? Wih1[o] : Wsi[o - (size_t)G4 * H_];
        Hh = d_WxH; Ll = d_WxL;
    } else if ((idx -= SZ_WX) < SZ_WX) {
        o = idx;
        v = (o < (size_t)G4 * H_) ? Whh1[o] : Wsh[o - (size_t)G4 * H_];
        Hh = d_WhH; Ll = d_WhL;
    } else if ((idx -= SZ_WX) < SZ_WB) {
        o = idx;
        int n = (int)(o >> 11), k = (int)(o & (K2 - 1));
        v = (k < H_) ? Wih2[((size_t)n << 10) + k] : Whh2[((size_t)n << 10) + k - H_];
        Hh = d_WbH; Ll = d_WbL;
    } else if ((idx -= SZ_WB) < SZ_VID) {
        o = idx; v = video[o]; Hh = d_VidH; Ll = d_VidL;
    } else return;
    __half hi = __float2half(v);
    __half lo = __float2half(v - __half2float(hi));
    Hh[o] = hi; Ll[o] = lo;
}

// ---------------- launch -----------------------------------------------------
extern "C" void kernel_launch(void* const* d_in, const int* in_sizes, int n_in,
                              void* d_out, int out_size)
{
    const float* video = (const float*)d_in[0];
    const float* Wemb  = (const float*)d_in[1];
    const float* bemb  = (const float*)d_in[2];
    const float* Wih1  = (const float*)d_in[3];
    const float* Whh1  = (const float*)d_in[4];
    const float* b1    = (const float*)d_in[5];
    const float* Wsi   = (const float*)d_in[6];
    const float* Wsh   = (const float*)d_in[7];
    const float* bbd   = (const float*)d_in[8];
    const float* vs    = (const float*)d_in[9];
    const float* Wih2  = (const float*)d_in[10];
    const float* Whh2  = (const float*)d_in[11];

    __half *pVidH,*pVidL,*pWembH,*pWembL,*pVH,*pVL,*pWxH,*pWxL;
    float *pbx,*pGXZ;
    cudaGetSymbolAddress((void**)&pVidH, d_VidH);  cudaGetSymbolAddress((void**)&pVidL, d_VidL);
    cudaGetSymbolAddress((void**)&pWembH,d_WembH); cudaGetSymbolAddress((void**)&pWembL,d_WembL);
    cudaGetSymbolAddress((void**)&pVH,   d_VH);    cudaGetSymbolAddress((void**)&pVL,   d_VL);
    cudaGetSymbolAddress((void**)&pWxH,  d_WxH);   cudaGetSymbolAddress((void**)&pWxL,  d_WxL);
    cudaGetSymbolAddress((void**)&pbx,   d_bx);
    cudaGetSymbolAddress((void**)&pGXZ,  d_GXZ);

    cudaFuncSetAttribute(gemm_h<1,1,1,3>, cudaFuncAttributeMaxDynamicSharedMemorySize, 2*40960);
    cudaFuncSetAttribute(gemm_h<1,0,0,2>, cudaFuncAttributeMaxDynamicSharedMemorySize, 3*30720);
    cudaFuncSetAttribute(gemm_h<1,0,0,3>, cudaFuncAttributeMaxDynamicSharedMemorySize, 2*40960);
    cudaFuncSetAttribute(scan_persist, cudaFuncAttributeMaxDynamicSharedMemorySize, SCAN_SMEM);

    int nsm = 148;
    cudaDeviceGetAttribute(&nsm, cudaDevAttrMultiProcessorCount, 0);
    const int G = nsm;   // 1 CTA/SM persistent scan

    // launch #1: fused state/bias init
    prep_state<<<(B_*K2 + 255) / 256, 256>>>(b1, bbd);
    // launch #2: all fp16 hi/lo splits fused
    {
        const size_t total = (size_t)H_*F_ + 2*(size_t)NA*H_ + (size_t)G4*K2 + (size_t)B_*T_*F_;
        split_all<<<(int)((total + 255) / 256), 256>>>(Wemb, Wih1, Wsi, Whh1, Wsh, Wih2, Whh2, video);
    }

    // launch #3: V = relu(video @ Wemb^T + bemb) -> fp16 split (rows b*T+t), 3-pass
    gemm_h<1,1,1,3><<<dim3(H_/128, (B_*T_)/128), 256, 2*40960>>>(
        pVidH, pVidL, (size_t)128 * F_, F_,
        pWembH, pWembL, nullptr, bemb, pVH, pVL, F_, H_, 0);
    // launches #4,#5: GXZ = V @ [Wih1;Wsi]^T + [b1;b_bd]
    gemm_h<1,0,0,2><<<dim3(32, (B_*T_)/128), 256, 3*30720>>>(
        pVH, pVL, (size_t)H_, T_ * H_,
        pWxH, pWxL, pGXZ, pbx, nullptr, nullptr, H_, NA, 0);
    gemm_h<1,0,0,3><<<dim3(4, (B_*T_)/128), 256, 2*40960>>>(
        pVH, pVL, (size_t)H_, T_ * H_,
        pWxH, pWxL, pGXZ, pbx, nullptr, nullptr, H_, NA, 32);

    // launch #6 (ncu -s 5 target): persistent fused scan over T
    scan_persist<<<G, 256, SCAN_SMEM>>>(vs, (float*)d_out);
}